// round 10
// baseline (speedup 1.0000x reference)
#include <cuda_runtime.h>
#include <math.h>

// ---------------- constants ----------------
#define HS 256
#define WS 256
#define NPIX 65536          // 256*256
#define N4M 4194304         // 2048*2048
#define W8 2048

// ---------------- device scratch ----------------
__device__ float g_x[256 * NPIX];   // conv_a output (relu), [co][y][x], 64MB
__device__ float g_wt[9 * 128 * 256]; // transposed conv_a weights [tap][ci][co]
__device__ float g_S[N4M];          // raw scores 2048x2048
__device__ float g_P[N4M];          // pool result
__device__ float g_T[N4M];          // separable temp
__device__ float g_M[N4M];          // max mask (0/1 as float)
__device__ float g_A[N4M];          // supp_scores / final scores
__device__ float g_U[N4M];          // supp mask (0/1 as float)

__device__ unsigned g_hist[4096];
__device__ unsigned g_state[8];     // [0..4]=digits d1..d5, [5]=rank
__device__ unsigned g_cnt;
__device__ float    g_wval[1024];
__device__ unsigned g_widx[1024];

// =================================================================
// weight transpose: OIHW w[co][ci][ky][kx] -> g_wt[tap][ci][co]
// =================================================================
__global__ void transpose_w_k(const float* __restrict__ w, float* __restrict__ wt) {
    int idx = blockIdx.x * blockDim.x + threadIdx.x;   // 294912
    if (idx >= 256 * 128 * 9) return;
    int co = idx / 1152;
    int r = idx - co * 1152;
    int ci = r / 9;
    int tap = r - ci * 9;
    wt[tap * 32768 + ci * 256 + co] = w[idx];
}

// =================================================================
// conv_a: 3x3 conv 128->256 + bias + relu, SAME padding. NCHW.
// Accumulation order: single sequential FMA chain per output in
// (ky,kx) OUTER, ci INNER (0..127) order — matching XLA-CPU/Eigen
// HWIO contraction (ci fastest).
// Block: 64 co x 16x16 px tile, 256 threads, 8co x 8px per thread.
// Whole 128-ci input patch resident in dynamic smem (217KB).
// =================================================================
__global__ __launch_bounds__(256, 1)
void conv_a_k(const float* __restrict__ in, const float* __restrict__ wt,
              const float* __restrict__ bias, float* __restrict__ xout) {
    extern __shared__ float dsm[];
    float* sIn = dsm;                 // [128][18][20] = 46080 floats
    float* sW = dsm + 46080;          // [128][64] per tap = 8192 floats

    int tid = threadIdx.x;
    int bx = blockIdx.x, by = blockIdx.y;
    int coB = blockIdx.z * 64;
    int tc = tid >> 5;            // warp id 0..7 -> co group
    int tp = tid & 31;
    int prow = tp >> 1;           // 0..15
    int pcol = (tp & 1) * 8;      // 0 or 8

    // load full input patch: 128 ci x 18 x 18 (zero pad)
    for (int e = tid; e < 128 * 18 * 18; e += 256) {
        int ci = e / 324;
        int rem = e - ci * 324;
        int iy = rem / 18;
        int ix = rem - iy * 18;
        int gy = by * 16 + iy - 1;
        int gx = bx * 16 + ix - 1;
        float v = 0.0f;
        if (gy >= 0 && gy < HS && gx >= 0 && gx < WS)
            v = in[ci * NPIX + gy * WS + gx];
        sIn[ci * 360 + iy * 20 + ix] = v;
    }

    float acc[8][8];
#pragma unroll
    for (int i = 0; i < 8; i++)
#pragma unroll
        for (int j = 0; j < 8; j++) acc[i][j] = 0.0f;

    __syncthreads();

    for (int tap = 0; tap < 9; ++tap) {
        int ky = tap / 3;
        int kx = tap - ky * 3;
        // load this tap's weights [128ci][64co] (coalesced from g_wt)
        for (int e = tid; e < 128 * 64; e += 256) {
            int ci = e >> 6;
            int co = e & 63;
            sW[e] = wt[tap * 32768 + ci * 256 + coB + co];
        }
        __syncthreads();

#pragma unroll 2
        for (int ci = 0; ci < 128; ++ci) {
            float wv[8], iv[8];
            const float* ibase = &sIn[ci * 360 + (prow + ky) * 20 + pcol + kx];
#pragma unroll
            for (int j = 0; j < 8; j++) iv[j] = ibase[j];
#pragma unroll
            for (int i = 0; i < 8; i++) wv[i] = sW[ci * 64 + tc * 8 + i];
#pragma unroll
            for (int i = 0; i < 8; i++)
#pragma unroll
                for (int j = 0; j < 8; j++)
                    acc[i][j] = fmaf(wv[i], iv[j], acc[i][j]);
        }
        __syncthreads();
    }

    int oy = by * 16 + prow;
    int ox = bx * 16 + pcol;
#pragma unroll
    for (int i = 0; i < 8; i++) {
        float bv = bias[coB + tc * 8 + i];
        int cbase = (coB + tc * 8 + i) * NPIX + oy * WS + ox;
#pragma unroll
        for (int j = 0; j < 8; j++)
            xout[cbase + j] = fmaxf(acc[i][j] + bv, 0.0f);
    }
}

// =================================================================
// conv_b (1x1 256->65) + bias + softmax(drop dustbin) + depth-to-space
// ci-chain sequential 0..255 (matches HWIO 1x1 contraction order).
// Softmax in double (stable, near-exact).
// =================================================================
__global__ __launch_bounds__(128)
void conv_b_k(const float* __restrict__ w1, const float* __restrict__ b1,
              const float* __restrict__ x, float* __restrict__ S) {
    __shared__ float xs[32][128];
    __shared__ float ws[32][66];
    int tid = threadIdx.x;
    int pbase = blockIdx.x * 128;

    float acc[65];
#pragma unroll
    for (int o = 0; o < 65; o++) acc[o] = 0.0f;

    for (int cc = 0; cc < 8; ++cc) {
        int ci0 = cc * 32;
        for (int e = tid; e < 32 * 128; e += 128) {
            int ci = e >> 7;
            int p = e & 127;
            xs[ci][p] = x[(ci0 + ci) * NPIX + pbase + p];
        }
        for (int e = tid; e < 32 * 65; e += 128) {
            int ci = e / 65;
            int o = e - ci * 65;
            ws[ci][o] = w1[o * 256 + ci0 + ci];
        }
        __syncthreads();
#pragma unroll 1
        for (int ci = 0; ci < 32; ++ci) {
            float xv = xs[ci][tid];
#pragma unroll
            for (int o = 0; o < 65; o++)
                acc[o] = fmaf(ws[ci][o], xv, acc[o]);
        }
        __syncthreads();
    }

#pragma unroll
    for (int o = 0; o < 65; o++) acc[o] = acc[o] + b1[o];

    float mx = acc[0];
#pragma unroll
    for (int o = 1; o < 65; o++) mx = fmaxf(mx, acc[o]);

    double sum = 0.0;
#pragma unroll
    for (int o = 0; o < 65; o++) {
        float e = (float)exp((double)acc[o] - (double)mx);
        acc[o] = e;
        sum += (double)e;
    }

    int p = pbase + tid;
    int y = p >> 8;
    int xq = p & 255;
#pragma unroll
    for (int o = 0; o < 64; o++) {
        int rr = y * 8 + (o >> 3);
        int cc2 = xq * 8 + (o & 7);
        S[rr * W8 + cc2] = (float)((double)acc[o] / sum);
    }
}

// =================================================================
// separable 9-tap max pools over 2048x2048, -inf padding
// =================================================================
__global__ void pool_h_k(const float* __restrict__ in, float* __restrict__ out) {
    const float NEGINF = __int_as_float(0xff800000);
    int idx = blockIdx.x * blockDim.x + threadIdx.x;  // 524288
    int r = idx >> 8;
    int g = idx & 255;
    int c0 = g * 8;
    float v[16];
#pragma unroll
    for (int j = 0; j < 16; j++) {
        int c = c0 - 4 + j;
        v[j] = (c >= 0 && c < W8) ? in[r * W8 + c] : NEGINF;
    }
#pragma unroll
    for (int i = 0; i < 8; i++) {
        float m = v[i];
#pragma unroll
        for (int j = 1; j < 9; j++) m = fmaxf(m, v[i + j]);
        out[r * W8 + c0 + i] = m;
    }
}

__global__ void pool_v_k(const float* __restrict__ in, float* __restrict__ out) {
    const float NEGINF = __int_as_float(0xff800000);
    int idx = blockIdx.x * blockDim.x + threadIdx.x;  // 524288
    int c = idx & 2047;
    int g = idx >> 11;
    int r0 = g * 8;
    float v[16];
#pragma unroll
    for (int j = 0; j < 16; j++) {
        int rr = r0 - 4 + j;
        v[j] = (rr >= 0 && rr < W8) ? in[rr * W8 + c] : NEGINF;
    }
#pragma unroll
    for (int i = 0; i < 8; i++) {
        float m = v[i];
#pragma unroll
        for (int j = 1; j < 9; j++) m = fmaxf(m, v[i + j]);
        out[(r0 + i) * W8 + c] = m;
    }
}

// ---------------- NMS elementwise ----------------
__global__ void mask_init_k(const float* __restrict__ S, const float* __restrict__ P,
                            float* __restrict__ M) {
    int i = blockIdx.x * blockDim.x + threadIdx.x;
    M[i] = (S[i] == P[i]) ? 1.0f : 0.0f;
}
__global__ void supp_k(const float* __restrict__ S, const float* __restrict__ P,
                       float* __restrict__ U, float* __restrict__ A) {
    int i = blockIdx.x * blockDim.x + threadIdx.x;
    bool u = P[i] > 0.0f;
    U[i] = u ? 1.0f : 0.0f;
    A[i] = u ? 0.0f : S[i];
}
__global__ void upd_k(const float* __restrict__ A, const float* __restrict__ P,
                      const float* __restrict__ U, float* __restrict__ M) {
    int i = blockIdx.x * blockDim.x + threadIdx.x;
    bool nm = (A[i] == P[i]) && (U[i] == 0.0f);
    M[i] = ((M[i] > 0.0f) || nm) ? 1.0f : 0.0f;
}
__global__ void final_k(const float* __restrict__ S, const float* __restrict__ M,
                        float* __restrict__ A) {
    int i = blockIdx.x * blockDim.x + threadIdx.x;
    A[i] = (M[i] > 0.0f) ? S[i] : 0.0f;
}

// =================================================================
// exact top-1024 select: (value desc, index asc) via hierarchical
// radix select on monotonic 32-bit value key + 22-bit index
// =================================================================
__device__ __forceinline__ unsigned monokey(const float* __restrict__ F, int i,
                                            float* pv) {
    float f = F[i];
    int r = i >> 11;
    int c = i & 2047;
    // reference border check: upper bounds are H8*8-4 (vacuous). lower only.
    bool valid = (f > 0.005f) && (r >= 4) && (c >= 4);
    float v = valid ? f : -1.0f;
    *pv = v;
    unsigned u = __float_as_uint(v);
    return (u & 0x80000000u) ? ~u : (u | 0x80000000u);
}

__global__ void select_init_k() {
    int t = threadIdx.x;
    g_wval[t] = -2.0f;
    g_widx[t] = 0;
    if (t == 0) { g_state[5] = 1024; g_cnt = 0; }
}

__global__ void clear_hist_k() {
    int t = blockIdx.x * blockDim.x + threadIdx.x;
    if (t < 4096) g_hist[t] = 0;
}

__global__ void hist_k(const float* __restrict__ F, int stage) {
    __shared__ unsigned sh[4096];
    for (int i = threadIdx.x; i < 4096; i += blockDim.x) sh[i] = 0;
    __syncthreads();
    unsigned d1 = g_state[0], d2 = g_state[1], d3 = g_state[2], d4 = g_state[3];
    unsigned V = (d1 << 20) | (d2 << 8) | d3;
    for (int i = blockIdx.x * blockDim.x + threadIdx.x; i < N4M;
         i += gridDim.x * blockDim.x) {
        float v;
        unsigned m = monokey(F, i, &v);
        int bin = -1;
        unsigned idx = (unsigned)i;
        switch (stage) {
            case 1: bin = m >> 20; break;
            case 2: if ((m >> 20) == d1) bin = (m >> 8) & 0xFFF; break;
            case 3: if ((m >> 8) == ((d1 << 12) | d2)) bin = m & 0xFF; break;
            case 4: if (m == V) bin = idx >> 11; break;
            case 5: if (m == V && (idx >> 11) == d4) bin = idx & 0x7FF; break;
        }
        if (bin >= 0) atomicAdd(&sh[bin], 1u);
    }
    __syncthreads();
    for (int i = threadIdx.x; i < 4096; i += blockDim.x)
        if (sh[i]) atomicAdd(&g_hist[i], sh[i]);
}

__global__ void resolve_k(int stage) {
    __shared__ unsigned ps[1024];
    int t = threadIdx.x;
    bool asc = (stage >= 4);
    unsigned r = g_state[5];
    unsigned loc[4];
    unsigned lsum = 0;
#pragma unroll
    for (int j = 0; j < 4; j++) {
        int p = t * 4 + j;
        int bin = asc ? p : (4095 - p);
        loc[j] = g_hist[bin];
        lsum += loc[j];
    }
    ps[t] = lsum;
    __syncthreads();
    for (int off = 1; off < 1024; off <<= 1) {
        unsigned v = (t >= off) ? ps[t - off] : 0u;
        __syncthreads();
        ps[t] += v;
        __syncthreads();
    }
    unsigned cum = ps[t] - lsum;
#pragma unroll
    for (int j = 0; j < 4; j++) {
        if (cum < r && r <= cum + loc[j]) {
            int p = t * 4 + j;
            int bin = asc ? p : (4095 - p);
            g_state[stage - 1] = (unsigned)bin;
            g_state[5] = r - cum;
        }
        cum += loc[j];
    }
}

__global__ void collect_k(const float* __restrict__ F) {
    unsigned d1 = g_state[0], d2 = g_state[1], d3 = g_state[2];
    unsigned d4 = g_state[3], d5 = g_state[4];
    unsigned V = (d1 << 20) | (d2 << 8) | d3;
    unsigned It = (d4 << 11) | d5;
    for (int i = blockIdx.x * blockDim.x + threadIdx.x; i < N4M;
         i += gridDim.x * blockDim.x) {
        float v;
        unsigned m = monokey(F, i, &v);
        bool keep = (m > V) || (m == V && ((unsigned)i) <= It);
        if (keep) {
            unsigned pos = atomicAdd(&g_cnt, 1u);
            if (pos < 1024) { g_wval[pos] = v; g_widx[pos] = (unsigned)i; }
        }
    }
}

__global__ void sort_write_k(float* __restrict__ out) {
    __shared__ unsigned long long sk[1024];
    int t = threadIdx.x;
    unsigned idx = g_widx[t];
    float v = g_wval[t];
    unsigned u = __float_as_uint(v);
    unsigned m = (u & 0x80000000u) ? ~u : (u | 0x80000000u);
    sk[t] = (((unsigned long long)m) << 22) | ((~idx) & 0x3FFFFFu);
    __syncthreads();
    for (int k = 2; k <= 1024; k <<= 1) {
        for (int j = k >> 1; j > 0; j >>= 1) {
            int ixj = t ^ j;
            if (ixj > t) {
                unsigned long long a = sk[t], b = sk[ixj];
                bool dirAsc = ((t & k) == 0);
                if ((a > b) == dirAsc) { sk[t] = b; sk[ixj] = a; }
            }
            __syncthreads();
        }
    }
    unsigned long long key = sk[1023 - t];
    unsigned ii = (~(unsigned)key) & 0x3FFFFFu;
    unsigned mm = (unsigned)(key >> 22);
    unsigned uu = (mm & 0x80000000u) ? (mm & 0x7FFFFFFFu) : ~mm;
    float val = __uint_as_float(uu);
    out[2 * t + 0] = (float)(ii & 2047);   // x = col
    out[2 * t + 1] = (float)(ii >> 11);    // y = row
    out[2048 + t] = val;
}

// =================================================================
// launcher
// =================================================================
extern "C" void kernel_launch(void* const* d_in, const int* in_sizes, int n_in,
                              void* d_out, int out_size) {
    (void)in_sizes; (void)n_in; (void)out_size;
    const float* enc = (const float*)d_in[0];
    const float* caw = (const float*)d_in[1];
    const float* cab = (const float*)d_in[2];
    const float* cbw = (const float*)d_in[3];
    const float* cbb = (const float*)d_in[4];

    float *pX, *pWT, *pS, *pP, *pT, *pM, *pA, *pU;
    cudaGetSymbolAddress((void**)&pX, g_x);
    cudaGetSymbolAddress((void**)&pWT, g_wt);
    cudaGetSymbolAddress((void**)&pS, g_S);
    cudaGetSymbolAddress((void**)&pP, g_P);
    cudaGetSymbolAddress((void**)&pT, g_T);
    cudaGetSymbolAddress((void**)&pM, g_M);
    cudaGetSymbolAddress((void**)&pA, g_A);
    cudaGetSymbolAddress((void**)&pU, g_U);

    // unconditional (no static guards allowed): host-side attribute set,
    // not a stream op — identical work on every call.
    cudaFuncSetAttribute(conv_a_k, cudaFuncAttributeMaxDynamicSharedMemorySize,
                         220 * 1024);

    transpose_w_k<<<288, 1024>>>(caw, pWT);
    conv_a_k<<<dim3(16, 16, 4), 256, 217088>>>(enc, pWT, cab, pX);
    conv_b_k<<<512, 128>>>(cbw, cbb, pX, pS);

    // simple_nms
    pool_h_k<<<2048, 256>>>(pS, pT);
    pool_v_k<<<2048, 256>>>(pT, pP);
    mask_init_k<<<16384, 256>>>(pS, pP, pM);
    for (int it = 0; it < 2; ++it) {
        pool_h_k<<<2048, 256>>>(pM, pT);
        pool_v_k<<<2048, 256>>>(pT, pP);
        supp_k<<<16384, 256>>>(pS, pP, pU, pA);
        pool_h_k<<<2048, 256>>>(pA, pT);
        pool_v_k<<<2048, 256>>>(pT, pP);
        upd_k<<<16384, 256>>>(pA, pP, pU, pM);
    }
    final_k<<<16384, 256>>>(pS, pM, pA);

    // exact top-1024
    select_init_k<<<1, 1024>>>();
    for (int stage = 1; stage <= 5; ++stage) {
        clear_hist_k<<<4, 1024>>>();
        hist_k<<<1024, 256>>>(pA, stage);
        resolve_k<<<1, 1024>>>(stage);
    }
    collect_k<<<1024, 256>>>(pA);
    sort_write_k<<<1, 1024>>>((float*)d_out);
}

// round 12
// speedup vs baseline: 1.0665x; 1.0665x over previous
#include <cuda_runtime.h>
#include <math.h>

// ---------------- constants ----------------
#define HS 256
#define WS 256
#define NPIX 65536          // 256*256
#define N4M 4194304         // 2048*2048
#define W8 2048

// ---------------- device scratch ----------------
__device__ float g_x[256 * NPIX];     // conv_a output (relu)
__device__ float g_wt[9 * 128 * 256]; // transposed conv_a weights [tap][ci][co]
__device__ float g_S[N4M];            // raw scores 2048x2048
__device__ float g_T[N4M];            // separable temp (row-max)
__device__ float g_M[N4M];            // max mask (0/1 float)
__device__ float g_A[N4M];            // supp_scores
__device__ float g_U[N4M];            // supp mask (0/1 float)
__device__ float g_F[N4M];            // final scores
__device__ unsigned long long g_cand[N4M]; // candidate (m<<32|idx)

__device__ unsigned g_hist5[5 * 4096];
__device__ unsigned g_state[8];       // [0..4]=digits, [5]=rank, [6]=cand count
__device__ unsigned g_cnt;            // winner count
__device__ float    g_wval[1024];
__device__ unsigned g_widx[1024];

// =================================================================
// weight transpose: OIHW w[co][ci][ky][kx] -> g_wt[tap][ci][co]
// =================================================================
__global__ void transpose_w_k(const float* __restrict__ w, float* __restrict__ wt) {
    int idx = blockIdx.x * blockDim.x + threadIdx.x;
    if (idx >= 256 * 128 * 9) return;
    int co = idx / 1152;
    int r = idx - co * 1152;
    int ci = r / 9;
    int tap = r - ci * 9;
    wt[tap * 32768 + ci * 256 + co] = w[idx];
}

// =================================================================
// conv_a: EXACT numerics proven in R10 — DO NOT TOUCH the FMA chain.
// (ky,kx) outer, ci inner 0..127 — matches XLA/Eigen HWIO contraction.
// =================================================================
__global__ __launch_bounds__(256, 1)
void conv_a_k(const float* __restrict__ in, const float* __restrict__ wt,
              const float* __restrict__ bias, float* __restrict__ xout) {
    extern __shared__ float dsm[];
    float* sIn = dsm;                 // [128][18][20]
    float* sW = dsm + 46080;          // [128][64] per tap

    int tid = threadIdx.x;
    int bx = blockIdx.x, by = blockIdx.y;
    int coB = blockIdx.z * 64;
    int tc = tid >> 5;
    int tp = tid & 31;
    int prow = tp >> 1;
    int pcol = (tp & 1) * 8;

    for (int e = tid; e < 128 * 18 * 18; e += 256) {
        int ci = e / 324;
        int rem = e - ci * 324;
        int iy = rem / 18;
        int ix = rem - iy * 18;
        int gy = by * 16 + iy - 1;
        int gx = bx * 16 + ix - 1;
        float v = 0.0f;
        if (gy >= 0 && gy < HS && gx >= 0 && gx < WS)
            v = in[ci * NPIX + gy * WS + gx];
        sIn[ci * 360 + iy * 20 + ix] = v;
    }

    float acc[8][8];
#pragma unroll
    for (int i = 0; i < 8; i++)
#pragma unroll
        for (int j = 0; j < 8; j++) acc[i][j] = 0.0f;

    __syncthreads();

    for (int tap = 0; tap < 9; ++tap) {
        int ky = tap / 3;
        int kx = tap - ky * 3;
        for (int e = tid; e < 128 * 64; e += 256) {
            int ci = e >> 6;
            int co = e & 63;
            sW[e] = wt[tap * 32768 + ci * 256 + coB + co];
        }
        __syncthreads();

#pragma unroll 2
        for (int ci = 0; ci < 128; ++ci) {
            float wv[8], iv[8];
            const float* ibase = &sIn[ci * 360 + (prow + ky) * 20 + pcol + kx];
#pragma unroll
            for (int j = 0; j < 8; j++) iv[j] = ibase[j];
#pragma unroll
            for (int i = 0; i < 8; i++) wv[i] = sW[ci * 64 + tc * 8 + i];
#pragma unroll
            for (int i = 0; i < 8; i++)
#pragma unroll
                for (int j = 0; j < 8; j++)
                    acc[i][j] = fmaf(wv[i], iv[j], acc[i][j]);
        }
        __syncthreads();
    }

    int oy = by * 16 + prow;
    int ox = bx * 16 + pcol;
#pragma unroll
    for (int i = 0; i < 8; i++) {
        float bv = bias[coB + tc * 8 + i];
        int cbase = (coB + tc * 8 + i) * NPIX + oy * WS + ox;
#pragma unroll
        for (int j = 0; j < 8; j++)
            xout[cbase + j] = fmaxf(acc[i][j] + bv, 0.0f);
    }
}

// =================================================================
// conv_b + softmax + depth-to-space (unchanged numerics)
// =================================================================
__global__ __launch_bounds__(128)
void conv_b_k(const float* __restrict__ w1, const float* __restrict__ b1,
              const float* __restrict__ x, float* __restrict__ S) {
    __shared__ float xs[32][128];
    __shared__ float ws[32][66];
    int tid = threadIdx.x;
    int pbase = blockIdx.x * 128;

    float acc[65];
#pragma unroll
    for (int o = 0; o < 65; o++) acc[o] = 0.0f;

    for (int cc = 0; cc < 8; ++cc) {
        int ci0 = cc * 32;
        for (int e = tid; e < 32 * 128; e += 128) {
            int ci = e >> 7;
            int p = e & 127;
            xs[ci][p] = x[(ci0 + ci) * NPIX + pbase + p];
        }
        for (int e = tid; e < 32 * 65; e += 128) {
            int ci = e / 65;
            int o = e - ci * 65;
            ws[ci][o] = w1[o * 256 + ci0 + ci];
        }
        __syncthreads();
#pragma unroll 1
        for (int ci = 0; ci < 32; ++ci) {
            float xv = xs[ci][tid];
#pragma unroll
            for (int o = 0; o < 65; o++)
                acc[o] = fmaf(ws[ci][o], xv, acc[o]);
        }
        __syncthreads();
    }

#pragma unroll
    for (int o = 0; o < 65; o++) acc[o] = acc[o] + b1[o];

    float mx = acc[0];
#pragma unroll
    for (int o = 1; o < 65; o++) mx = fmaxf(mx, acc[o]);

    double sum = 0.0;
#pragma unroll
    for (int o = 0; o < 65; o++) {
        float e = (float)exp((double)acc[o] - (double)mx);
        acc[o] = e;
        sum += (double)e;
    }

    int p = pbase + tid;
    int y = p >> 8;
    int xq = p & 255;
#pragma unroll
    for (int o = 0; o < 64; o++) {
        int rr = y * 8 + (o >> 3);
        int cc2 = xq * 8 + (o & 7);
        S[rr * W8 + cc2] = (float)((double)acc[o] / sum);
    }
}

// =================================================================
// NMS — separable 9-tap max pools, fused elementwise epilogues
// =================================================================
#define NEGINF __int_as_float(0xff800000)

// row max: thread handles row r, cols [c0, c0+8), via 4 aligned LDG.128
__global__ void pool_h_k(const float* __restrict__ in, float* __restrict__ out) {
    int idx = blockIdx.x * blockDim.x + threadIdx.x;  // 524288
    int r = idx >> 8;
    int g = idx & 255;
    int c0 = g * 8;
    const float4* p = (const float4*)(in + r * W8);
    float4 ninf = make_float4(NEGINF, NEGINF, NEGINF, NEGINF);
    float4 q0 = (g > 0) ? p[2 * g - 1] : ninf;
    float4 q1 = p[2 * g];
    float4 q2 = p[2 * g + 1];
    float4 q3 = (g < 255) ? p[2 * g + 2] : ninf;
    float v[16] = {q0.x, q0.y, q0.z, q0.w, q1.x, q1.y, q1.z, q1.w,
                   q2.x, q2.y, q2.z, q2.w, q3.x, q3.y, q3.z, q3.w};
    float o[8];
#pragma unroll
    for (int i = 0; i < 8; i++) {
        float m = v[i];
#pragma unroll
        for (int j = 1; j < 9; j++) m = fmaxf(m, v[i + j]);
        o[i] = m;
    }
    float4* po = (float4*)(out + r * W8 + c0);
    po[0] = make_float4(o[0], o[1], o[2], o[3]);
    po[1] = make_float4(o[4], o[5], o[6], o[7]);
}

// column-max helper: loads v[16] for col c rows [r0-4, r0+12)
#define PV_LOAD(T)                                                     \
    int idx = blockIdx.x * blockDim.x + threadIdx.x;                   \
    int c = idx & 2047;                                                \
    int g = idx >> 11;                                                 \
    int r0 = g * 8;                                                    \
    float v[16];                                                       \
    _Pragma("unroll")                                                  \
    for (int j = 0; j < 16; j++) {                                     \
        int rr = r0 - 4 + j;                                           \
        v[j] = (rr >= 0 && rr < W8) ? (T)[rr * W8 + c] : NEGINF;       \
    }

// col max + mask_init: M = (S == maxpool(S)) ? 1 : 0
__global__ void pv_mask_k(const float* __restrict__ T, const float* __restrict__ S,
                          float* __restrict__ M) {
    PV_LOAD(T)
#pragma unroll
    for (int i = 0; i < 8; i++) {
        float m = v[i];
#pragma unroll
        for (int j = 1; j < 9; j++) m = fmaxf(m, v[i + j]);
        int o = (r0 + i) * W8 + c;
        M[o] = (S[o] == m) ? 1.0f : 0.0f;
    }
}

// col max + supp: U = (pool>0); A = U ? 0 : S
__global__ void pv_supp_k(const float* __restrict__ T, const float* __restrict__ S,
                          float* __restrict__ U, float* __restrict__ A) {
    PV_LOAD(T)
#pragma unroll
    for (int i = 0; i < 8; i++) {
        float m = v[i];
#pragma unroll
        for (int j = 1; j < 9; j++) m = fmaxf(m, v[i + j]);
        int o = (r0 + i) * W8 + c;
        bool u = m > 0.0f;
        U[o] = u ? 1.0f : 0.0f;
        A[o] = u ? 0.0f : S[o];
    }
}

// col max + update mask: M |= (A == pool(A)) & ~U
__global__ void pv_upd_k(const float* __restrict__ T, const float* __restrict__ A,
                         const float* __restrict__ U, float* __restrict__ M) {
    PV_LOAD(T)
#pragma unroll
    for (int i = 0; i < 8; i++) {
        float m = v[i];
#pragma unroll
        for (int j = 1; j < 9; j++) m = fmaxf(m, v[i + j]);
        int o = (r0 + i) * W8 + c;
        bool nm = (A[o] == m) && (U[o] == 0.0f);
        M[o] = ((M[o] > 0.0f) || nm) ? 1.0f : 0.0f;
    }
}

__device__ __forceinline__ unsigned monokey_v(float f, int r, int c, float* pv) {
    bool valid = (f > 0.005f) && (r >= 4) && (c >= 4);
    float v = valid ? f : -1.0f;
    *pv = v;
    unsigned u = __float_as_uint(v);
    return (u & 0x80000000u) ? ~u : (u | 0x80000000u);
}

// final iteration: M2 mask + final scores F + stage-1 histogram (fused)
__global__ void pv_upd2_k(const float* __restrict__ T, const float* __restrict__ A,
                          const float* __restrict__ U, const float* __restrict__ M,
                          const float* __restrict__ S, float* __restrict__ F) {
    __shared__ unsigned sh[4096];
    for (int i = threadIdx.x; i < 4096; i += blockDim.x) sh[i] = 0;
    __syncthreads();
    PV_LOAD(T)
#pragma unroll
    for (int i = 0; i < 8; i++) {
        float m = v[i];
#pragma unroll
        for (int j = 1; j < 9; j++) m = fmaxf(m, v[i + j]);
        int rr = r0 + i;
        int o = rr * W8 + c;
        bool nm = (A[o] == m) && (U[o] == 0.0f);
        bool mm = (M[o] > 0.0f) || nm;
        float a = mm ? S[o] : 0.0f;
        F[o] = a;
        float dummy;
        unsigned mk = monokey_v(a, rr, c, &dummy);
        atomicAdd(&sh[mk >> 20], 1u);
    }
    __syncthreads();
    for (int i = threadIdx.x; i < 4096; i += blockDim.x)
        if (sh[i]) atomicAdd(&g_hist5[i], sh[i]);
}

// =================================================================
// exact top-1024 select — candidate-compacted radix
// =================================================================
__global__ void select_init_k() {
    int t = threadIdx.x;
    g_wval[t] = -2.0f;
    g_widx[t] = 0;
    for (int i = t; i < 5 * 4096; i += 1024) g_hist5[i] = 0;
    if (t == 0) { g_state[5] = 1024; g_state[6] = 0; g_cnt = 0; }
}

__global__ void resolve_k(int stage) {
    __shared__ unsigned ps[1024];
    const unsigned* hist = g_hist5 + (stage - 1) * 4096;
    int t = threadIdx.x;
    bool asc = (stage >= 4);
    unsigned r = g_state[5];
    unsigned loc[4];
    unsigned lsum = 0;
#pragma unroll
    for (int j = 0; j < 4; j++) {
        int p = t * 4 + j;
        int bin = asc ? p : (4095 - p);
        loc[j] = hist[bin];
        lsum += loc[j];
    }
    ps[t] = lsum;
    __syncthreads();
    for (int off = 1; off < 1024; off <<= 1) {
        unsigned v = (t >= off) ? ps[t - off] : 0u;
        __syncthreads();
        ps[t] += v;
        __syncthreads();
    }
    unsigned cum = ps[t] - lsum;
#pragma unroll
    for (int j = 0; j < 4; j++) {
        if (cum < r && r <= cum + loc[j]) {
            int p = t * 4 + j;
            int bin = asc ? p : (4095 - p);
            g_state[stage - 1] = (unsigned)bin;
            g_state[5] = r - cum;
        }
        cum += loc[j];
    }
}

// full scan: prefix > d1 -> guaranteed winner; == d1 -> candidate
__global__ void compact_k(const float* __restrict__ F) {
    unsigned d1 = g_state[0];
    for (int i = blockIdx.x * blockDim.x + threadIdx.x; i < N4M;
         i += gridDim.x * blockDim.x) {
        float f = F[i];
        int r = i >> 11;
        int c = i & 2047;
        float val;
        unsigned m = monokey_v(f, r, c, &val);
        unsigned t = m >> 20;
        if (t > d1) {
            unsigned pos = atomicAdd(&g_cnt, 1u);
            if (pos < 1024) { g_wval[pos] = val; g_widx[pos] = (unsigned)i; }
        } else if (t == d1) {
            unsigned pos = atomicAdd(&g_state[6], 1u);
            g_cand[pos] = (((unsigned long long)m) << 32) | (unsigned)i;
        }
    }
}

__global__ void hist_cand_k(int stage) {
    __shared__ unsigned sh[4096];
    for (int i = threadIdx.x; i < 4096; i += blockDim.x) sh[i] = 0;
    __syncthreads();
    unsigned n = g_state[6];
    unsigned d1 = g_state[0], d2 = g_state[1], d3 = g_state[2], d4 = g_state[3];
    unsigned V = (d1 << 20) | (d2 << 8) | d3;
    for (unsigned k = blockIdx.x * blockDim.x + threadIdx.x; k < n;
         k += gridDim.x * blockDim.x) {
        unsigned long long e = g_cand[k];
        unsigned m = (unsigned)(e >> 32);
        unsigned idx = (unsigned)e;
        int bin = -1;
        switch (stage) {
            case 2: bin = (m >> 8) & 0xFFF; break;
            case 3: if ((m >> 8) == ((d1 << 12) | d2)) bin = m & 0xFF; break;
            case 4: if (m == V) bin = idx >> 11; break;
            case 5: if (m == V && (idx >> 11) == d4) bin = idx & 0x7FF; break;
        }
        if (bin >= 0) atomicAdd(&sh[bin], 1u);
    }
    __syncthreads();
    unsigned* hist = g_hist5 + (stage - 1) * 4096;
    for (int i = threadIdx.x; i < 4096; i += blockDim.x)
        if (sh[i]) atomicAdd(&hist[i], sh[i]);
}

__global__ void collect_cand_k() {
    unsigned n = g_state[6];
    unsigned d1 = g_state[0], d2 = g_state[1], d3 = g_state[2];
    unsigned d4 = g_state[3], d5 = g_state[4];
    unsigned V = (d1 << 20) | (d2 << 8) | d3;
    unsigned It = (d4 << 11) | d5;
    for (unsigned k = blockIdx.x * blockDim.x + threadIdx.x; k < n;
         k += gridDim.x * blockDim.x) {
        unsigned long long e = g_cand[k];
        unsigned m = (unsigned)(e >> 32);
        unsigned idx = (unsigned)e;
        bool keep = (m > V) || (m == V && idx <= It);
        if (keep) {
            unsigned pos = atomicAdd(&g_cnt, 1u);
            if (pos < 1024) {
                unsigned uu = (m & 0x80000000u) ? (m & 0x7FFFFFFFu) : ~m;
                g_wval[pos] = __uint_as_float(uu);
                g_widx[pos] = idx;
            }
        }
    }
}

__global__ void sort_write_k(float* __restrict__ out) {
    __shared__ unsigned long long sk[1024];
    int t = threadIdx.x;
    unsigned idx = g_widx[t];
    float v = g_wval[t];
    unsigned u = __float_as_uint(v);
    unsigned m = (u & 0x80000000u) ? ~u : (u | 0x80000000u);
    sk[t] = (((unsigned long long)m) << 22) | ((~idx) & 0x3FFFFFu);
    __syncthreads();
    for (int k = 2; k <= 1024; k <<= 1) {
        for (int j = k >> 1; j > 0; j >>= 1) {
            int ixj = t ^ j;
            if (ixj > t) {
                unsigned long long a = sk[t], b = sk[ixj];
                bool dirAsc = ((t & k) == 0);
                if ((a > b) == dirAsc) { sk[t] = b; sk[ixj] = a; }
            }
            __syncthreads();
        }
    }
    unsigned long long key = sk[1023 - t];
    unsigned ii = (~(unsigned)key) & 0x3FFFFFu;
    unsigned mm = (unsigned)(key >> 22);
    unsigned uu = (mm & 0x80000000u) ? (mm & 0x7FFFFFFFu) : ~mm;
    float val = __uint_as_float(uu);
    out[2 * t + 0] = (float)(ii & 2047);
    out[2 * t + 1] = (float)(ii >> 11);
    out[2048 + t] = val;
}

// =================================================================
// launcher
// =================================================================
extern "C" void kernel_launch(void* const* d_in, const int* in_sizes, int n_in,
                              void* d_out, int out_size) {
    (void)in_sizes; (void)n_in; (void)out_size;
    const float* enc = (const float*)d_in[0];
    const float* caw = (const float*)d_in[1];
    const float* cab = (const float*)d_in[2];
    const float* cbw = (const float*)d_in[3];
    const float* cbb = (const float*)d_in[4];

    float *pX, *pWT, *pS, *pT, *pM, *pA, *pU, *pF;
    cudaGetSymbolAddress((void**)&pX, g_x);
    cudaGetSymbolAddress((void**)&pWT, g_wt);
    cudaGetSymbolAddress((void**)&pS, g_S);
    cudaGetSymbolAddress((void**)&pT, g_T);
    cudaGetSymbolAddress((void**)&pM, g_M);
    cudaGetSymbolAddress((void**)&pA, g_A);
    cudaGetSymbolAddress((void**)&pU, g_U);
    cudaGetSymbolAddress((void**)&pF, g_F);

    cudaFuncSetAttribute(conv_a_k, cudaFuncAttributeMaxDynamicSharedMemorySize,
                         220 * 1024);

    select_init_k<<<1, 1024>>>();   // clears hists + counters (before fused hist)

    transpose_w_k<<<288, 1024>>>(caw, pWT);
    conv_a_k<<<dim3(16, 16, 4), 256, 217088>>>(enc, pWT, cab, pX);
    conv_b_k<<<512, 128>>>(cbw, cbb, pX, pS);

    // simple_nms (fused)
    pool_h_k<<<2048, 256>>>(pS, pT);
    pv_mask_k<<<2048, 256>>>(pT, pS, pM);
    // iter 1
    pool_h_k<<<2048, 256>>>(pM, pT);
    pv_supp_k<<<2048, 256>>>(pT, pS, pU, pA);
    pool_h_k<<<2048, 256>>>(pA, pT);
    pv_upd_k<<<2048, 256>>>(pT, pA, pU, pM);
    // iter 2 + final + stage-1 hist
    pool_h_k<<<2048, 256>>>(pM, pT);
    pv_supp_k<<<2048, 256>>>(pT, pS, pU, pA);
    pool_h_k<<<2048, 256>>>(pA, pT);
    pv_upd2_k<<<2048, 256>>>(pT, pA, pU, pM, pS, pF);

    // top-1024: resolve stage 1, compact, then candidate-only stages
    resolve_k<<<1, 1024>>>(1);
    compact_k<<<1024, 256>>>(pF);
    for (int stage = 2; stage <= 5; ++stage) {
        hist_cand_k<<<128, 256>>>(stage);
        resolve_k<<<1, 1024>>>(stage);
    }
    collect_cand_k<<<128, 256>>>();
    sort_write_k<<<1, 1024>>>((float*)d_out);
}

// round 16
// speedup vs baseline: 1.1870x; 1.1130x over previous
#include <cuda_runtime.h>
#include <math.h>

// ---------------- constants ----------------
#define HS 256
#define WS 256
#define NPIX 65536          // 256*256
#define N4M 4194304         // 2048*2048
#define W8 2048

// ---------------- device scratch ----------------
__device__ float g_x[256 * NPIX];     // conv_a output (relu)
__device__ float g_wt[9 * 128 * 256]; // transposed conv_a weights [tap][ci][co]
__device__ float g_S[N4M];            // raw scores 2048x2048
__device__ float g_T[N4M];            // separable temp (row-max)
__device__ float g_M[N4M];            // max mask (0/1 float)
__device__ float g_A[N4M];            // supp_scores
__device__ float g_U[N4M];            // supp mask (0/1 float)
__device__ float g_F[N4M];            // final scores
__device__ unsigned long long g_cand[N4M]; // candidate (m<<32|idx)

__device__ unsigned g_hist5[5 * 4096];
__device__ unsigned g_state[8];       // [0..4]=digits, [5]=rank, [6]=cand count
__device__ unsigned g_cnt;            // winner count
__device__ float    g_wval[1024];
__device__ unsigned g_widx[1024];

// =================================================================
// weight transpose: OIHW w[co][ci][ky][kx] -> g_wt[tap][ci][co]
// =================================================================
__global__ void transpose_w_k(const float* __restrict__ w, float* __restrict__ wt) {
    int idx = blockIdx.x * blockDim.x + threadIdx.x;
    if (idx >= 256 * 128 * 9) return;
    int co = idx / 1152;
    int r = idx - co * 1152;
    int ci = r / 9;
    int tap = r - ci * 9;
    wt[tap * 32768 + ci * 256 + co] = w[idx];
}

// =================================================================
// conv_a: EXACT numerics proven in R10 — DO NOT TOUCH the FMA chain.
// (ky,kx) outer, ci inner 0..127 — matches XLA/Eigen HWIO contraction.
// =================================================================
__global__ __launch_bounds__(256, 1)
void conv_a_k(const float* __restrict__ in, const float* __restrict__ wt,
              const float* __restrict__ bias, float* __restrict__ xout) {
    extern __shared__ float dsm[];
    float* sIn = dsm;                 // [128][18][20]
    float* sW = dsm + 46080;          // [128][64] per tap

    int tid = threadIdx.x;
    int bx = blockIdx.x, by = blockIdx.y;
    int coB = blockIdx.z * 64;
    int tc = tid >> 5;
    int tp = tid & 31;
    int prow = tp >> 1;
    int pcol = (tp & 1) * 8;

    for (int e = tid; e < 128 * 18 * 18; e += 256) {
        int ci = e / 324;
        int rem = e - ci * 324;
        int iy = rem / 18;
        int ix = rem - iy * 18;
        int gy = by * 16 + iy - 1;
        int gx = bx * 16 + ix - 1;
        float v = 0.0f;
        if (gy >= 0 && gy < HS && gx >= 0 && gx < WS)
            v = in[ci * NPIX + gy * WS + gx];
        sIn[ci * 360 + iy * 20 + ix] = v;
    }

    float acc[8][8];
#pragma unroll
    for (int i = 0; i < 8; i++)
#pragma unroll
        for (int j = 0; j < 8; j++) acc[i][j] = 0.0f;

    __syncthreads();

    for (int tap = 0; tap < 9; ++tap) {
        int ky = tap / 3;
        int kx = tap - ky * 3;
        for (int e = tid; e < 128 * 64; e += 256) {
            int ci = e >> 6;
            int co = e & 63;
            sW[e] = wt[tap * 32768 + ci * 256 + coB + co];
        }
        __syncthreads();

#pragma unroll 2
        for (int ci = 0; ci < 128; ++ci) {
            float wv[8], iv[8];
            const float* ibase = &sIn[ci * 360 + (prow + ky) * 20 + pcol + kx];
#pragma unroll
            for (int j = 0; j < 8; j++) iv[j] = ibase[j];
#pragma unroll
            for (int i = 0; i < 8; i++) wv[i] = sW[ci * 64 + tc * 8 + i];
#pragma unroll
            for (int i = 0; i < 8; i++)
#pragma unroll
                for (int j = 0; j < 8; j++)
                    acc[i][j] = fmaf(wv[i], iv[j], acc[i][j]);
        }
        __syncthreads();
    }

    int oy = by * 16 + prow;
    int ox = bx * 16 + pcol;
#pragma unroll
    for (int i = 0; i < 8; i++) {
        float bv = bias[coB + tc * 8 + i];
        int cbase = (coB + tc * 8 + i) * NPIX + oy * WS + ox;
#pragma unroll
        for (int j = 0; j < 8; j++)
            xout[cbase + j] = fmaxf(acc[i][j] + bv, 0.0f);
    }
}

// =================================================================
// conv_b (1x1 256->65) + bias + softmax + depth-to-space — v2
// Block = 32 pixels x 4 channel-groups (128 thr). Each thread owns
// <=17 channels; per-channel ci-chain 0..255 sequential (bit-identical
// to v1). fmaxf max exact under any order; double softmax sum uses
// 4 partials (perturbation ~1e-16 rel — negligible vs 1e-5 gaps).
// =================================================================
__global__ __launch_bounds__(128)
void conv_b_k(const float* __restrict__ w1, const float* __restrict__ b1,
              const float* __restrict__ x, float* __restrict__ S) {
    __shared__ float xs[32][32];      // ci-chunk x pixels
    __shared__ float ws[32][66];      // ci-chunk x channel
    __shared__ float smax[4][32];
    __shared__ double ssum[4][32];

    int tid = threadIdx.x;
    int p = tid & 31;                 // pixel lane
    int grp = tid >> 5;               // channel group 0..3
    int o0 = grp * 17;                // 0,17,34,51
    int nch = (grp == 3) ? 14 : 17;   // 51..64 inclusive
    int pbase = blockIdx.x * 32;

    float acc[17];
#pragma unroll
    for (int i = 0; i < 17; i++) acc[i] = 0.0f;

    for (int cc = 0; cc < 8; ++cc) {
        int ci0 = cc * 32;
        for (int e = tid; e < 32 * 32; e += 128) {
            int ci = e >> 5;
            int pp = e & 31;
            xs[ci][pp] = x[(ci0 + ci) * NPIX + pbase + pp];
        }
        for (int e = tid; e < 32 * 65; e += 128) {
            int ci = e / 65;
            int o = e - ci * 65;
            ws[ci][o] = w1[o * 256 + ci0 + ci];
        }
        __syncthreads();
#pragma unroll 1
        for (int ci = 0; ci < 32; ++ci) {
            float xv = xs[ci][p];
#pragma unroll
            for (int i = 0; i < 17; i++)
                if (i < nch) acc[i] = fmaf(ws[ci][o0 + i], xv, acc[i]);
        }
        __syncthreads();
    }

#pragma unroll
    for (int i = 0; i < 17; i++)
        if (i < nch) acc[i] = acc[i] + b1[o0 + i];

    float mx = acc[0];
#pragma unroll
    for (int i = 1; i < 17; i++)
        if (i < nch) mx = fmaxf(mx, acc[i]);
    smax[grp][p] = mx;
    __syncthreads();
    mx = fmaxf(fmaxf(smax[0][p], smax[1][p]), fmaxf(smax[2][p], smax[3][p]));

    float ev[17];
    double psum = 0.0;
#pragma unroll
    for (int i = 0; i < 17; i++) {
        if (i < nch) {
            float e = (float)exp((double)acc[i] - (double)mx);
            ev[i] = e;
            psum += (double)e;
        }
    }
    ssum[grp][p] = psum;
    __syncthreads();
    double sum = (ssum[0][p] + ssum[1][p]) + (ssum[2][p] + ssum[3][p]);

    int pix = pbase + p;
    int y = pix >> 8;
    int xq = pix & 255;
#pragma unroll
    for (int i = 0; i < 17; i++) {
        int o = o0 + i;
        if (i < nch && o < 64) {
            int rr = y * 8 + (o >> 3);
            int cc2 = xq * 8 + (o & 7);
            S[rr * W8 + cc2] = (float)((double)ev[i] / sum);
        }
    }
}

// =================================================================
// NMS — separable 9-tap max pools, fused elementwise epilogues
// =================================================================
#define NEGINF __int_as_float(0xff800000)

__global__ void pool_h_k(const float* __restrict__ in, float* __restrict__ out) {
    int idx = blockIdx.x * blockDim.x + threadIdx.x;  // 524288
    int r = idx >> 8;
    int g = idx & 255;
    int c0 = g * 8;
    const float4* p = (const float4*)(in + r * W8);
    float4 ninf = make_float4(NEGINF, NEGINF, NEGINF, NEGINF);
    float4 q0 = (g > 0) ? p[2 * g - 1] : ninf;
    float4 q1 = p[2 * g];
    float4 q2 = p[2 * g + 1];
    float4 q3 = (g < 255) ? p[2 * g + 2] : ninf;
    float v[16] = {q0.x, q0.y, q0.z, q0.w, q1.x, q1.y, q1.z, q1.w,
                   q2.x, q2.y, q2.z, q2.w, q3.x, q3.y, q3.z, q3.w};
    float o[8];
#pragma unroll
    for (int i = 0; i < 8; i++) {
        float m = v[i];
#pragma unroll
        for (int j = 1; j < 9; j++) m = fmaxf(m, v[i + j]);
        o[i] = m;
    }
    float4* po = (float4*)(out + r * W8 + c0);
    po[0] = make_float4(o[0], o[1], o[2], o[3]);
    po[1] = make_float4(o[4], o[5], o[6], o[7]);
}

#define PV_LOAD(T)                                                     \
    int idx = blockIdx.x * blockDim.x + threadIdx.x;                   \
    int c = idx & 2047;                                                \
    int g = idx >> 11;                                                 \
    int r0 = g * 8;                                                    \
    float v[16];                                                       \
    _Pragma("unroll")                                                  \
    for (int j = 0; j < 16; j++) {                                     \
        int rr = r0 - 4 + j;                                           \
        v[j] = (rr >= 0 && rr < W8) ? (T)[rr * W8 + c] : NEGINF;       \
    }

__global__ void pv_mask_k(const float* __restrict__ T, const float* __restrict__ S,
                          float* __restrict__ M) {
    PV_LOAD(T)
#pragma unroll
    for (int i = 0; i < 8; i++) {
        float m = v[i];
#pragma unroll
        for (int j = 1; j < 9; j++) m = fmaxf(m, v[i + j]);
        int o = (r0 + i) * W8 + c;
        M[o] = (S[o] == m) ? 1.0f : 0.0f;
    }
}

__global__ void pv_supp_k(const float* __restrict__ T, const float* __restrict__ S,
                          float* __restrict__ U, float* __restrict__ A) {
    PV_LOAD(T)
#pragma unroll
    for (int i = 0; i < 8; i++) {
        float m = v[i];
#pragma unroll
        for (int j = 1; j < 9; j++) m = fmaxf(m, v[i + j]);
        int o = (r0 + i) * W8 + c;
        bool u = m > 0.0f;
        U[o] = u ? 1.0f : 0.0f;
        A[o] = u ? 0.0f : S[o];
    }
}

__global__ void pv_upd_k(const float* __restrict__ T, const float* __restrict__ A,
                         const float* __restrict__ U, float* __restrict__ M) {
    PV_LOAD(T)
#pragma unroll
    for (int i = 0; i < 8; i++) {
        float m = v[i];
#pragma unroll
        for (int j = 1; j < 9; j++) m = fmaxf(m, v[i + j]);
        int o = (r0 + i) * W8 + c;
        bool nm = (A[o] == m) && (U[o] == 0.0f);
        M[o] = ((M[o] > 0.0f) || nm) ? 1.0f : 0.0f;
    }
}

__device__ __forceinline__ unsigned monokey_v(float f, int r, int c, float* pv) {
    bool valid = (f > 0.005f) && (r >= 4) && (c >= 4);
    float v = valid ? f : -1.0f;
    *pv = v;
    unsigned u = __float_as_uint(v);
    return (u & 0x80000000u) ? ~u : (u | 0x80000000u);
}

__global__ void pv_upd2_k(const float* __restrict__ T, const float* __restrict__ A,
                          const float* __restrict__ U, const float* __restrict__ M,
                          const float* __restrict__ S, float* __restrict__ F) {
    __shared__ unsigned sh[4096];
    for (int i = threadIdx.x; i < 4096; i += blockDim.x) sh[i] = 0;
    __syncthreads();
    PV_LOAD(T)
#pragma unroll
    for (int i = 0; i < 8; i++) {
        float m = v[i];
#pragma unroll
        for (int j = 1; j < 9; j++) m = fmaxf(m, v[i + j]);
        int rr = r0 + i;
        int o = rr * W8 + c;
        bool nm = (A[o] == m) && (U[o] == 0.0f);
        bool mm = (M[o] > 0.0f) || nm;
        float a = mm ? S[o] : 0.0f;
        F[o] = a;
        float dummy;
        unsigned mk = monokey_v(a, rr, c, &dummy);
        atomicAdd(&sh[mk >> 20], 1u);
    }
    __syncthreads();
    for (int i = threadIdx.x; i < 4096; i += blockDim.x)
        if (sh[i]) atomicAdd(&g_hist5[i], sh[i]);
}

// =================================================================
// exact top-1024 select — candidate-compacted radix
// =================================================================
__global__ void select_init_k() {
    int t = threadIdx.x;
    g_wval[t] = -2.0f;
    g_widx[t] = 0;
    for (int i = t; i < 5 * 4096; i += 1024) g_hist5[i] = 0;
    if (t == 0) { g_state[5] = 1024; g_state[6] = 0; g_cnt = 0; }
}

__global__ void resolve_k(int stage) {
    __shared__ unsigned ps[1024];
    const unsigned* hist = g_hist5 + (stage - 1) * 4096;
    int t = threadIdx.x;
    bool asc = (stage >= 4);
    unsigned r = g_state[5];
    unsigned loc[4];
    unsigned lsum = 0;
#pragma unroll
    for (int j = 0; j < 4; j++) {
        int p = t * 4 + j;
        int bin = asc ? p : (4095 - p);
        loc[j] = hist[bin];
        lsum += loc[j];
    }
    ps[t] = lsum;
    __syncthreads();
    for (int off = 1; off < 1024; off <<= 1) {
        unsigned v = (t >= off) ? ps[t - off] : 0u;
        __syncthreads();
        ps[t] += v;
        __syncthreads();
    }
    unsigned cum = ps[t] - lsum;
#pragma unroll
    for (int j = 0; j < 4; j++) {
        if (cum < r && r <= cum + loc[j]) {
            int p = t * 4 + j;
            int bin = asc ? p : (4095 - p);
            g_state[stage - 1] = (unsigned)bin;
            g_state[5] = r - cum;
        }
        cum += loc[j];
    }
}

__global__ void compact_k(const float* __restrict__ F) {
    unsigned d1 = g_state[0];
    for (int i = blockIdx.x * blockDim.x + threadIdx.x; i < N4M;
         i += gridDim.x * blockDim.x) {
        float f = F[i];
        int r = i >> 11;
        int c = i & 2047;
        float val;
        unsigned m = monokey_v(f, r, c, &val);
        unsigned t = m >> 20;
        if (t > d1) {
            unsigned pos = atomicAdd(&g_cnt, 1u);
            if (pos < 1024) { g_wval[pos] = val; g_widx[pos] = (unsigned)i; }
        } else if (t == d1) {
            unsigned pos = atomicAdd(&g_state[6], 1u);
            g_cand[pos] = (((unsigned long long)m) << 32) | (unsigned)i;
        }
    }
}

__global__ void hist_cand_k(int stage) {
    __shared__ unsigned sh[4096];
    for (int i = threadIdx.x; i < 4096; i += blockDim.x) sh[i] = 0;
    __syncthreads();
    unsigned n = g_state[6];
    unsigned d1 = g_state[0], d2 = g_state[1], d3 = g_state[2], d4 = g_state[3];
    unsigned V = (d1 << 20) | (d2 << 8) | d3;
    for (unsigned k = blockIdx.x * blockDim.x + threadIdx.x; k < n;
         k += gridDim.x * blockDim.x) {
        unsigned long long e = g_cand[k];
        unsigned m = (unsigned)(e >> 32);
        unsigned idx = (unsigned)e;
        int bin = -1;
        switch (stage) {
            case 2: bin = (m >> 8) & 0xFFF; break;
            case 3: if ((m >> 8) == ((d1 << 12) | d2)) bin = m & 0xFF; break;
            case 4: if (m == V) bin = idx >> 11; break;
            case 5: if (m == V && (idx >> 11) == d4) bin = idx & 0x7FF; break;
        }
        if (bin >= 0) atomicAdd(&sh[bin], 1u);
    }
    __syncthreads();
    unsigned* hist = g_hist5 + (stage - 1) * 4096;
    for (int i = threadIdx.x; i < 4096; i += blockDim.x)
        if (sh[i]) atomicAdd(&hist[i], sh[i]);
}

__global__ void collect_cand_k() {
    unsigned n = g_state[6];
    unsigned d1 = g_state[0], d2 = g_state[1], d3 = g_state[2];
    unsigned d4 = g_state[3], d5 = g_state[4];
    unsigned V = (d1 << 20) | (d2 << 8) | d3;
    unsigned It = (d4 << 11) | d5;
    for (unsigned k = blockIdx.x * blockDim.x + threadIdx.x; k < n;
         k += gridDim.x * blockDim.x) {
        unsigned long long e = g_cand[k];
        unsigned m = (unsigned)(e >> 32);
        unsigned idx = (unsigned)e;
        bool keep = (m > V) || (m == V && idx <= It);
        if (keep) {
            unsigned pos = atomicAdd(&g_cnt, 1u);
            if (pos < 1024) {
                unsigned uu = (m & 0x80000000u) ? (m & 0x7FFFFFFFu) : ~m;
                g_wval[pos] = __uint_as_float(uu);
                g_widx[pos] = idx;
            }
        }
    }
}

__global__ void sort_write_k(float* __restrict__ out) {
    __shared__ unsigned long long sk[1024];
    int t = threadIdx.x;
    unsigned idx = g_widx[t];
    float v = g_wval[t];
    unsigned u = __float_as_uint(v);
    unsigned m = (u & 0x80000000u) ? ~u : (u | 0x80000000u);
    sk[t] = (((unsigned long long)m) << 22) | ((~idx) & 0x3FFFFFu);
    __syncthreads();
    for (int k = 2; k <= 1024; k <<= 1) {
        for (int j = k >> 1; j > 0; j >>= 1) {
            int ixj = t ^ j;
            if (ixj > t) {
                unsigned long long a = sk[t], b = sk[ixj];
                bool dirAsc = ((t & k) == 0);
                if ((a > b) == dirAsc) { sk[t] = b; sk[ixj] = a; }
            }
            __syncthreads();
        }
    }
    unsigned long long key = sk[1023 - t];
    unsigned ii = (~(unsigned)key) & 0x3FFFFFu;
    unsigned mm = (unsigned)(key >> 22);
    unsigned uu = (mm & 0x80000000u) ? (mm & 0x7FFFFFFFu) : ~mm;
    float val = __uint_as_float(uu);
    out[2 * t + 0] = (float)(ii & 2047);
    out[2 * t + 1] = (float)(ii >> 11);
    out[2048 + t] = val;
}

// =================================================================
// launcher
// =================================================================
extern "C" void kernel_launch(void* const* d_in, const int* in_sizes, int n_in,
                              void* d_out, int out_size) {
    (void)in_sizes; (void)n_in; (void)out_size;
    const float* enc = (const float*)d_in[0];
    const float* caw = (const float*)d_in[1];
    const float* cab = (const float*)d_in[2];
    const float* cbw = (const float*)d_in[3];
    const float* cbb = (const float*)d_in[4];

    float *pX, *pWT, *pS, *pT, *pM, *pA, *pU, *pF;
    cudaGetSymbolAddress((void**)&pX, g_x);
    cudaGetSymbolAddress((void**)&pWT, g_wt);
    cudaGetSymbolAddress((void**)&pS, g_S);
    cudaGetSymbolAddress((void**)&pT, g_T);
    cudaGetSymbolAddress((void**)&pM, g_M);
    cudaGetSymbolAddress((void**)&pA, g_A);
    cudaGetSymbolAddress((void**)&pU, g_U);
    cudaGetSymbolAddress((void**)&pF, g_F);

    cudaFuncSetAttribute(conv_a_k, cudaFuncAttributeMaxDynamicSharedMemorySize,
                         220 * 1024);

    select_init_k<<<1, 1024>>>();

    transpose_w_k<<<288, 1024>>>(caw, pWT);
    conv_a_k<<<dim3(16, 16, 4), 256, 217088>>>(enc, pWT, cab, pX);
    conv_b_k<<<2048, 128>>>(cbw, cbb, pX, pS);

    // simple_nms (fused)
    pool_h_k<<<2048, 256>>>(pS, pT);
    pv_mask_k<<<2048, 256>>>(pT, pS, pM);
    pool_h_k<<<2048, 256>>>(pM, pT);
    pv_supp_k<<<2048, 256>>>(pT, pS, pU, pA);
    pool_h_k<<<2048, 256>>>(pA, pT);
    pv_upd_k<<<2048, 256>>>(pT, pA, pU, pM);
    pool_h_k<<<2048, 256>>>(pM, pT);
    pv_supp_k<<<2048, 256>>>(pT, pS, pU, pA);
    pool_h_k<<<2048, 256>>>(pA, pT);
    pv_upd2_k<<<2048, 256>>>(pT, pA, pU, pM, pS, pF);

    // top-1024: resolve stage 1, compact, then candidate-only stages
    resolve_k<<<1, 1024>>>(1);
    compact_k<<<1024, 256>>>(pF);
    for (int stage = 2; stage <= 5; ++stage) {
        hist_cand_k<<<128, 256>>>(stage);
        resolve_k<<<1, 1024>>>(stage);
    }
    collect_cand_k<<<128, 256>>>();
    sort_write_k<<<1, 1024>>>((float*)d_out);
}